// round 12
// baseline (speedup 1.0000x reference)
#include <cuda_runtime.h>

// QuadcopterCollisionFcn:
//   inputs: state (B,N,6) f32, sdf (256,256,256) f32, sdf_grad (unused), T (3,10) f32
//   output: (B,N) f32 in {-10000, 0}
//
// R11 base (ILP2, spatially-paired early-exit rounds of 2, bit-exact folded
// template offsets) + L2 residency hint: all SDF loads use
// createpolicy.fractional.L2::evict_last so the SDF working set stays pinned
// in L2 across graph replays (L2 persists between launches; only L1 flushes).
// Profiling showed ~78MB DRAM traffic/launch (~17% L2 hit rate) = the real
// bottleneck (DRAM random-sector bandwidth), which this attacks directly.

#define G 256
#define TPB 128
#define EPB 256   // elements per block = 2 * TPB

__device__ __forceinline__ unsigned long long mk_evict_last_policy()
{
    unsigned long long pol;
    asm("createpolicy.fractional.L2::evict_last.b64 %0, 1.0;" : "=l"(pol));
    return pol;
}

__device__ __forceinline__ float4 ldg_pol4(const float4* a, unsigned long long pol)
{
    float4 v;
    asm("ld.global.nc.L2::cache_hint.v4.f32 {%0,%1,%2,%3}, [%4], %5;"
        : "=f"(v.x), "=f"(v.y), "=f"(v.z), "=f"(v.w)
        : "l"(a), "l"(pol));
    return v;
}

__device__ __forceinline__ float ldg_pol1(const float* a, unsigned long long pol)
{
    float v;
    asm("ld.global.nc.L2::cache_hint.f32 %0, [%1], %2;"
        : "=f"(v) : "l"(a), "l"(pol));
    return v;
}

__device__ __forceinline__ float sample_sdf(const float* __restrict__ sdf,
                                            unsigned long long pol,
                                            float X, float Y, float Z)
{
    float pcx = fminf(fmaxf(X, 0.0f), 255.0f);
    float pcy = fminf(fmaxf(Y, 0.0f), 255.0f);
    float pcz = fminf(fmaxf(Z, 0.0f), 255.0f);

    int ix = min((int)floorf(pcx), G - 2);
    int iy = min((int)floorf(pcy), G - 2);
    int iz = min((int)floorf(pcz), G - 2);

    float fx = pcx - (float)ix;
    float fy = pcy - (float)iy;
    float fz = pcz - (float)iz;

    int q = iz & ~3;          // 16B-aligned z quad
    int r = iz & 3;
    int base = (ix << 16) | (iy << 8) | q;

    const float4* p4 = (const float4*)(sdf + base);
    float4 F00 = ldg_pol4(p4, pol);                 // (dx=0, dy=0)
    float4 F01 = ldg_pol4(p4 + (G / 4), pol);       // (dx=0, dy=1)
    float4 F10 = ldg_pol4(p4 + (G * G / 4), pol);   // (dx=1, dy=0)
    float4 F11 = ldg_pol4(p4 + (G * G / 4) + (G / 4), pol);

    float e00 = 0.0f, e01 = 0.0f, e10 = 0.0f, e11 = 0.0f;
    if (r == 3) {              // fixup: z+1 spills into next quad (q+4 <= 255)
        e00 = ldg_pol1(&sdf[base + 4], pol);
        e01 = ldg_pol1(&sdf[base + G + 4], pol);
        e10 = ldg_pol1(&sdf[base + G * G + 4], pol);
        e11 = ldg_pol1(&sdf[base + G * G + G + 4], pol);
    }

    float c000 = (r == 0) ? F00.x : (r == 1) ? F00.y : (r == 2) ? F00.z : F00.w;
    float c001 = (r == 0) ? F00.y : (r == 1) ? F00.z : (r == 2) ? F00.w : e00;
    float c010 = (r == 0) ? F01.x : (r == 1) ? F01.y : (r == 2) ? F01.z : F01.w;
    float c011 = (r == 0) ? F01.y : (r == 1) ? F01.z : (r == 2) ? F01.w : e01;
    float c100 = (r == 0) ? F10.x : (r == 1) ? F10.y : (r == 2) ? F10.z : F10.w;
    float c101 = (r == 0) ? F10.y : (r == 1) ? F10.z : (r == 2) ? F10.w : e10;
    float c110 = (r == 0) ? F11.x : (r == 1) ? F11.y : (r == 2) ? F11.z : F11.w;
    float c111 = (r == 0) ? F11.y : (r == 1) ? F11.z : (r == 2) ? F11.w : e11;

    // identical lerp chain to the reference (x, then y, then z)
    float omfx = 1.0f - fx;
    float c00 = c000 * omfx + c100 * fx;
    float c01 = c001 * omfx + c101 * fx;
    float c10 = c010 * omfx + c110 * fx;
    float c11 = c011 * omfx + c111 * fx;

    float omfy = 1.0f - fy;
    float c0 = c00 * omfy + c10 * fy;
    float c1 = c01 * omfy + c11 * fy;

    return c0 * (1.0f - fz) + c1 * fz;
}

// Per-element persistent state (precomputed exact offsets)
struct Elem {
    float px, py, pz;
    float Ax, Ay, Az;      // -0.5*col2  (m0; m5 = -this)
    float o1x, o1y, o1z;   // A + 4*col0  (m1; m7 = -this)
    float o2x, o2y, o2z;   // A - 4*col0  (m2; m6 = -this)
    float o3x, o3y, o3z;   // A + 4*col1  (m3; m9 = -this)
    float o4x, o4y, o4z;   // A - 4*col1  (m4; m8 = -this)
};

__device__ __forceinline__ void setup_elem(const float* s, Elem& e)
{
    float px = s[0], py = s[1], pz = s[2];
    float ax = s[3], ay = s[4], az = s[5];

    // ang reversed -> (az, ay, ax); R = Rz(az) @ Ry(ay) @ Rx(ax)
    float sz, cz, sy, cy, sx, cx;
    sincosf(az, &sz, &cz);
    sincosf(ay, &sy, &cy);
    sincosf(ax, &sx, &cx);

    float r00 = cz * cy;
    float r01 = cz * sy * sx - sz * cx;
    float r02 = cz * sy * cx + sz * sx;
    float r10 = sz * cy;
    float r11 = sz * sy * sx + cz * cx;
    float r12 = sz * sy * cx - cz * sx;
    float r20 = -sy;
    float r21 = cy * sx;
    float r22 = cy * cx;

    // exact folds (T entries {0,+-0.5,+-4} are powers of two)
    float P0x = 4.0f * r00, P0y = 4.0f * r10, P0z = 4.0f * r20;
    float P1x = 4.0f * r01, P1y = 4.0f * r11, P1z = 4.0f * r21;
    e.Ax = -0.5f * r02; e.Ay = -0.5f * r12; e.Az = -0.5f * r22;

    e.px = px; e.py = py; e.pz = pz;
    e.o1x = P0x + e.Ax; e.o1y = P0y + e.Ay; e.o1z = P0z + e.Az;
    e.o2x = e.Ax - P0x; e.o2y = e.Ay - P0y; e.o2z = e.Az - P0z;
    e.o3x = P1x + e.Ax; e.o3y = P1y + e.Ay; e.o3z = P1z + e.Az;
    e.o4x = e.Ax - P1x; e.o4y = e.Ay - P1y; e.o4z = e.Az - P1z;
}

__device__ __forceinline__ float round_pair(const float* __restrict__ sdf,
                                            unsigned long long pol,
                                            const Elem& e,
                                            float ox, float oy, float oz,
                                            float nx, float ny, float nz)
{
    float dA = sample_sdf(sdf, pol, ox + e.px, oy + e.py, oz + e.pz);
    float dB = sample_sdf(sdf, pol, nx + e.px, ny + e.py, nz + e.pz);
    return fminf(dA, dB);
}

__global__ __launch_bounds__(TPB, 7)
void quad_collision_kernel(const float* __restrict__ state,
                           const float* __restrict__ sdf,
                           float* __restrict__ out,
                           int total)
{
    __shared__ float s_state[EPB * 6];

    int block_base = blockIdx.x * EPB;

    // Coalesced stage of this block's 256 state rows.
    {
        const float4* src = (const float4*)(state + (size_t)block_base * 6);
        float4* dst = (float4*)s_state;
        int nvec = (EPB * 6) / 4;  // 384
        int avail = (total - block_base) * 6 / 4;
        for (int i = threadIdx.x; i < nvec; i += TPB) {
            if (i < avail) dst[i] = src[i];
        }
    }
    __syncthreads();

    int ia = block_base + threadIdx.x;
    int ib = ia + TPB;
    bool va = ia < total;
    bool vb = ib < total;
    if (!va) return;   // if ia OOB, ib is too

    unsigned long long pol = mk_evict_last_policy();

    Elem A, B;
    setup_elem(s_state + threadIdx.x * 6, A);
    if (vb) setup_elem(s_state + (threadIdx.x + TPB) * 6, B);

    float dminA, dminB = -1.0f;  // invalid B counts as "decided"

    // Paired rounds: each round = one rotor's two sample points (1 unit apart).
    // r1: (m0 = +A, m5 = -A)
    {
        dminA = round_pair(sdf, pol, A,  A.Ax,  A.Ay,  A.Az,  -A.Ax, -A.Ay, -A.Az);
        if (vb)
            dminB = round_pair(sdf, pol, B,  B.Ax,  B.Ay,  B.Az,  -B.Ax, -B.Ay, -B.Az);
    }

    // r2: (m1 = +(A+P0), m6 = -(A-P0))
    if (dminA >= 0.0f || dminB >= 0.0f) {
        if (dminA >= 0.0f)
            dminA = fminf(dminA, round_pair(sdf, pol, A, A.o1x, A.o1y, A.o1z,
                                                         -A.o2x, -A.o2y, -A.o2z));
        if (dminB >= 0.0f)
            dminB = fminf(dminB, round_pair(sdf, pol, B, B.o1x, B.o1y, B.o1z,
                                                         -B.o2x, -B.o2y, -B.o2z));
        // r3: (m2 = +(A-P0), m7 = -(A+P0))
        if (dminA >= 0.0f || dminB >= 0.0f) {
            if (dminA >= 0.0f)
                dminA = fminf(dminA, round_pair(sdf, pol, A, A.o2x, A.o2y, A.o2z,
                                                             -A.o1x, -A.o1y, -A.o1z));
            if (dminB >= 0.0f)
                dminB = fminf(dminB, round_pair(sdf, pol, B, B.o2x, B.o2y, B.o2z,
                                                             -B.o1x, -B.o1y, -B.o1z));
            // r4: (m3 = +(A+P1), m8 = -(A-P1))
            if (dminA >= 0.0f || dminB >= 0.0f) {
                if (dminA >= 0.0f)
                    dminA = fminf(dminA, round_pair(sdf, pol, A, A.o3x, A.o3y, A.o3z,
                                                                 -A.o4x, -A.o4y, -A.o4z));
                if (dminB >= 0.0f)
                    dminB = fminf(dminB, round_pair(sdf, pol, B, B.o3x, B.o3y, B.o3z,
                                                                 -B.o4x, -B.o4y, -B.o4z));
                // r5: (m4 = +(A-P1), m9 = -(A+P1))
                if (dminA >= 0.0f || dminB >= 0.0f) {
                    if (dminA >= 0.0f)
                        dminA = fminf(dminA, round_pair(sdf, pol, A, A.o4x, A.o4y, A.o4z,
                                                                     -A.o3x, -A.o3y, -A.o3z));
                    if (dminB >= 0.0f)
                        dminB = fminf(dminB, round_pair(sdf, pol, B, B.o4x, B.o4y, B.o4z,
                                                                     -B.o3x, -B.o3y, -B.o3z));
                }
            }
        }
    }

    out[ia] = (dminA < 0.0f) ? -10000.0f : 0.0f;
    if (vb) out[ib] = (dminB < 0.0f) ? -10000.0f : 0.0f;
}

extern "C" void kernel_launch(void* const* d_in, const int* in_sizes, int n_in,
                              void* d_out, int out_size)
{
    const float* state = (const float*)d_in[0];
    const float* sdf   = (const float*)d_in[1];
    // d_in[2] = sdf_grad (unused), d_in[3] = T (constant-folded, entries {0,+-0.5,+-4})
    float* out = (float*)d_out;

    int total = in_sizes[0] / 6;  // B*N

    int blocks = (total + EPB - 1) / EPB;
    quad_collision_kernel<<<blocks, TPB>>>(state, sdf, out, total);
}

// round 13
// speedup vs baseline: 1.0721x; 1.0721x over previous
#include <cuda_runtime.h>

// QuadcopterCollisionFcn:
//   inputs: state (B,N,6) f32, sdf (256,256,256) f32, sdf_grad (unused), T (3,10) f32
//   output: (B,N) f32 in {-10000, 0}
//
// ILP2 chassis (elements i, i+128 per thread) with sample schedule (1,2,2,2,3):
// round 1 evaluates only the center sample (P(decide)=0.5), cutting expected
// samples/element 2.66 -> 2.34 (the L1tex divergent-replay wavefront volume is
// the measured bottleneck). Early exit per element via predication; output =
// any(d<0), order-independent. Per-sample math bit-identical to the validated
// rel_err==0.0 kernels (T entries {0,+-0.5,+-4} fold exactly).

#define G 256
#define TPB 128
#define EPB 256   // elements per block = 2 * TPB

__device__ __forceinline__ float sample_sdf(const float* __restrict__ sdf,
                                            float X, float Y, float Z)
{
    float pcx = fminf(fmaxf(X, 0.0f), 255.0f);
    float pcy = fminf(fmaxf(Y, 0.0f), 255.0f);
    float pcz = fminf(fmaxf(Z, 0.0f), 255.0f);

    int ix = min((int)floorf(pcx), G - 2);
    int iy = min((int)floorf(pcy), G - 2);
    int iz = min((int)floorf(pcz), G - 2);

    float fx = pcx - (float)ix;
    float fy = pcy - (float)iy;
    float fz = pcz - (float)iz;

    int q = iz & ~3;          // 16B-aligned z quad
    int r = iz & 3;
    int base = (ix << 16) | (iy << 8) | q;

    const float4* p4 = (const float4*)(sdf + base);
    float4 F00 = __ldg(p4);                 // (dx=0, dy=0)
    float4 F01 = __ldg(p4 + (G / 4));       // (dx=0, dy=1)
    float4 F10 = __ldg(p4 + (G * G / 4));   // (dx=1, dy=0)
    float4 F11 = __ldg(p4 + (G * G / 4) + (G / 4));

    float e00 = 0.0f, e01 = 0.0f, e10 = 0.0f, e11 = 0.0f;
    if (r == 3) {              // fixup: z+1 spills into next quad (q+4 <= 255)
        e00 = __ldg(&sdf[base + 4]);
        e01 = __ldg(&sdf[base + G + 4]);
        e10 = __ldg(&sdf[base + G * G + 4]);
        e11 = __ldg(&sdf[base + G * G + G + 4]);
    }

    float c000 = (r == 0) ? F00.x : (r == 1) ? F00.y : (r == 2) ? F00.z : F00.w;
    float c001 = (r == 0) ? F00.y : (r == 1) ? F00.z : (r == 2) ? F00.w : e00;
    float c010 = (r == 0) ? F01.x : (r == 1) ? F01.y : (r == 2) ? F01.z : F01.w;
    float c011 = (r == 0) ? F01.y : (r == 1) ? F01.z : (r == 2) ? F01.w : e01;
    float c100 = (r == 0) ? F10.x : (r == 1) ? F10.y : (r == 2) ? F10.z : F10.w;
    float c101 = (r == 0) ? F10.y : (r == 1) ? F10.z : (r == 2) ? F10.w : e10;
    float c110 = (r == 0) ? F11.x : (r == 1) ? F11.y : (r == 2) ? F11.z : F11.w;
    float c111 = (r == 0) ? F11.y : (r == 1) ? F11.z : (r == 2) ? F11.w : e11;

    // identical lerp chain to the reference (x, then y, then z)
    float omfx = 1.0f - fx;
    float c00 = c000 * omfx + c100 * fx;
    float c01 = c001 * omfx + c101 * fx;
    float c10 = c010 * omfx + c110 * fx;
    float c11 = c011 * omfx + c111 * fx;

    float omfy = 1.0f - fy;
    float c0 = c00 * omfy + c10 * fy;
    float c1 = c01 * omfy + c11 * fy;

    return c0 * (1.0f - fz) + c1 * fz;
}

// Per-element persistent state (precomputed exact offsets)
struct Elem {
    float px, py, pz;
    float Ax, Ay, Az;      // -0.5*col2  (m0; m5 = -this)
    float o1x, o1y, o1z;   // A + 4*col0  (m1; m7 = -this)
    float o2x, o2y, o2z;   // A - 4*col0  (m2; m6 = -this)
    float o3x, o3y, o3z;   // A + 4*col1  (m3; m9 = -this)
    float o4x, o4y, o4z;   // A - 4*col1  (m4; m8 = -this)
};

__device__ __forceinline__ void setup_elem(const float* s, Elem& e)
{
    float px = s[0], py = s[1], pz = s[2];
    float ax = s[3], ay = s[4], az = s[5];

    // ang reversed -> (az, ay, ax); R = Rz(az) @ Ry(ay) @ Rx(ax)
    float sz, cz, sy, cy, sx, cx;
    sincosf(az, &sz, &cz);
    sincosf(ay, &sy, &cy);
    sincosf(ax, &sx, &cx);

    float r00 = cz * cy;
    float r01 = cz * sy * sx - sz * cx;
    float r02 = cz * sy * cx + sz * sx;
    float r10 = sz * cy;
    float r11 = sz * sy * sx + cz * cx;
    float r12 = sz * sy * cx - cz * sx;
    float r20 = -sy;
    float r21 = cy * sx;
    float r22 = cy * cx;

    // exact folds (T entries {0,+-0.5,+-4} are powers of two)
    float P0x = 4.0f * r00, P0y = 4.0f * r10, P0z = 4.0f * r20;
    float P1x = 4.0f * r01, P1y = 4.0f * r11, P1z = 4.0f * r21;
    e.Ax = -0.5f * r02; e.Ay = -0.5f * r12; e.Az = -0.5f * r22;

    e.px = px; e.py = py; e.pz = pz;
    e.o1x = P0x + e.Ax; e.o1y = P0y + e.Ay; e.o1z = P0z + e.Az;
    e.o2x = e.Ax - P0x; e.o2y = e.Ay - P0y; e.o2z = e.Az - P0z;
    e.o3x = P1x + e.Ax; e.o3y = P1y + e.Ay; e.o3z = P1z + e.Az;
    e.o4x = e.Ax - P1x; e.o4y = e.Ay - P1y; e.o4z = e.Az - P1z;
}

__device__ __forceinline__ float round_pair(const float* __restrict__ sdf,
                                            const Elem& e,
                                            float ox, float oy, float oz,
                                            float nx, float ny, float nz)
{
    float dA = sample_sdf(sdf, ox + e.px, oy + e.py, oz + e.pz);
    float dB = sample_sdf(sdf, nx + e.px, ny + e.py, nz + e.pz);
    return fminf(dA, dB);
}

__global__ __launch_bounds__(TPB, 7)
void quad_collision_kernel(const float* __restrict__ state,
                           const float* __restrict__ sdf,
                           float* __restrict__ out,
                           int total)
{
    __shared__ float s_state[EPB * 6];

    int block_base = blockIdx.x * EPB;

    // Coalesced stage of this block's 256 state rows.
    {
        const float4* src = (const float4*)(state + (size_t)block_base * 6);
        float4* dst = (float4*)s_state;
        int nvec = (EPB * 6) / 4;  // 384
        int avail = (total - block_base) * 6 / 4;
        for (int i = threadIdx.x; i < nvec; i += TPB) {
            if (i < avail) dst[i] = src[i];
        }
    }
    __syncthreads();

    int ia = block_base + threadIdx.x;
    int ib = ia + TPB;
    bool va = ia < total;
    bool vb = ib < total;
    if (!va) return;   // if ia OOB, ib is too

    Elem A, B;
    setup_elem(s_state + threadIdx.x * 6, A);
    if (vb) setup_elem(s_state + (threadIdx.x + TPB) * 6, B);

    float dminA, dminB = -1.0f;  // invalid B counts as "decided"

    // round 1: m0 only (1 sample per element; P(decide) = 0.5)
    {
        dminA = sample_sdf(sdf, A.Ax + A.px, A.Ay + A.py, A.Az + A.pz);
        if (vb)
            dminB = sample_sdf(sdf, B.Ax + B.px, B.Ay + B.py, B.Az + B.pz);
    }

    // round 2: (m5 = -A, m1 = +o1)
    if (dminA >= 0.0f || dminB >= 0.0f) {
        if (dminA >= 0.0f)
            dminA = fminf(dminA, round_pair(sdf, A, -A.Ax, -A.Ay, -A.Az,
                                                    A.o1x, A.o1y, A.o1z));
        if (dminB >= 0.0f)
            dminB = fminf(dminB, round_pair(sdf, B, -B.Ax, -B.Ay, -B.Az,
                                                    B.o1x, B.o1y, B.o1z));
        // round 3: (m6 = -o2, m2 = +o2)
        if (dminA >= 0.0f || dminB >= 0.0f) {
            if (dminA >= 0.0f)
                dminA = fminf(dminA, round_pair(sdf, A, -A.o2x, -A.o2y, -A.o2z,
                                                        A.o2x, A.o2y, A.o2z));
            if (dminB >= 0.0f)
                dminB = fminf(dminB, round_pair(sdf, B, -B.o2x, -B.o2y, -B.o2z,
                                                        B.o2x, B.o2y, B.o2z));
            // round 4: (m7 = -o1, m3 = +o3)
            if (dminA >= 0.0f || dminB >= 0.0f) {
                if (dminA >= 0.0f)
                    dminA = fminf(dminA, round_pair(sdf, A, -A.o1x, -A.o1y, -A.o1z,
                                                            A.o3x, A.o3y, A.o3z));
                if (dminB >= 0.0f)
                    dminB = fminf(dminB, round_pair(sdf, B, -B.o1x, -B.o1y, -B.o1z,
                                                            B.o3x, B.o3y, B.o3z));
                // round 5: (m8 = -o4, m4 = +o4, m9 = -o3)
                if (dminA >= 0.0f || dminB >= 0.0f) {
                    if (dminA >= 0.0f) {
                        float a0 = sample_sdf(sdf, -A.o4x + A.px, -A.o4y + A.py, -A.o4z + A.pz);
                        float a1 = sample_sdf(sdf,  A.o4x + A.px,  A.o4y + A.py,  A.o4z + A.pz);
                        float a2 = sample_sdf(sdf, -A.o3x + A.px, -A.o3y + A.py, -A.o3z + A.pz);
                        dminA = fminf(dminA, fminf(a0, fminf(a1, a2)));
                    }
                    if (dminB >= 0.0f) {
                        float b0 = sample_sdf(sdf, -B.o4x + B.px, -B.o4y + B.py, -B.o4z + B.pz);
                        float b1 = sample_sdf(sdf,  B.o4x + B.px,  B.o4y + B.py,  B.o4z + B.pz);
                        float b2 = sample_sdf(sdf, -B.o3x + B.px, -B.o3y + B.py, -B.o3z + B.pz);
                        dminB = fminf(dminB, fminf(b0, fminf(b1, b2)));
                    }
                }
            }
        }
    }

    out[ia] = (dminA < 0.0f) ? -10000.0f : 0.0f;
    if (vb) out[ib] = (dminB < 0.0f) ? -10000.0f : 0.0f;
}

extern "C" void kernel_launch(void* const* d_in, const int* in_sizes, int n_in,
                              void* d_out, int out_size)
{
    const float* state = (const float*)d_in[0];
    const float* sdf   = (const float*)d_in[1];
    // d_in[2] = sdf_grad (unused), d_in[3] = T (constant-folded, entries {0,+-0.5,+-4})
    float* out = (float*)d_out;

    int total = in_sizes[0] / 6;  // B*N

    int blocks = (total + EPB - 1) / EPB;
    quad_collision_kernel<<<blocks, TPB>>>(state, sdf, out, total);
}